// round 15
// baseline (speedup 1.0000x reference)
#include <cuda_runtime.h>

// Problem constants (fixed by reference_code)
#define IN_F   256
#define N_ASS  4096
#define OUT_F  256
#define BATCH  128
#define ASS0   IN_F            // 256  : first associative neuron index
#define OUT0   (IN_F + N_ASS)  // 4352 : first output neuron index

// ELL strides (padded gather lists keyed by destination).
#define ELL1_S 64
#define ELL2_S 384

// Counter padding. L2 slice hash uses addr bits {8,10-27}; contiguous 4B
// counters collapsed onto ~4 slice-groups (R6 build=22us). 256B stride fixed
// most of it (R7 build=9.2us). cnt2 (205 atomics/counter) now gets 2KB stride
// to cover more hash bits + the 2KB die-interleave grain.
#define CPAD1 64    // 256B stride, 4096 counters (13 atomics each)
#define CPAD2 512   // 2KB stride,  256 counters (205 atomics each)

// Device scratch (no runtime allocation allowed). Zero-initialized at load;
// the hop kernels re-zero the counters after consuming them, so every graph
// replay sees counters == 0 on entry to the build kernel.
__device__ float g_xT  [IN_F  * BATCH];     // x transposed: [in_f][batch]
__device__ float g_HT  [N_ASS * BATCH];     // hidden acts transposed
__device__ int   g_cnt1[N_ASS * CPAD1];     // padded per-assoc in-degree counters
__device__ int   g_cnt2[OUT_F * CPAD2];     // padded per-output in-degree counters
__device__ int   g_e1src[N_ASS * ELL1_S];
__device__ float g_e1w  [N_ASS * ELL1_S];
__device__ int   g_e2src[OUT_F * ELL2_S];
__device__ float g_e2w  [OUT_F * ELL2_S];

// ---------------------------------------------------------------------------
// Kernel A (fused): transpose x -> xT, bucket hop1 edges, bucket hop2 edges
// (keep only dst >= OUT0). ALL edge arrays are streamed as front-batched
// int4/float4 loads (MLP=3 per thread) — R7 showed the predicated scalar
// src/w gathers touched 86% of lines anyway but serialized at MLP=1.
// ---------------------------------------------------------------------------
__global__ void __launch_bounds__(256)
build_kernel(const float* __restrict__ x,
             const int* __restrict__ in_src, const int* __restrict__ in_dst,
             const float* __restrict__ w_in, int E_in,
             const int* __restrict__ ass_src, const int* __restrict__ ass_dst,
             const float* __restrict__ w_ass, int E_ass) {
    const int t = blockIdx.x * blockDim.x + threadIdx.x;

    // --- transpose x (32768 elems) ---
    if (t < BATCH * IN_F) {
        int b = t >> 8;          // / IN_F
        int i = t & (IN_F - 1);  // % IN_F
        g_xT[i * BATCH + b] = x[t];
    }

    const int e = t * 4;

    // --- hop1 bucketing: 4 edges/thread, streamed wide loads, 4 independent
    //     predicate-free atomic chains ---
    if (e + 4 <= E_in) {
        int4   s4 = *reinterpret_cast<const int4*>  (in_src + e);
        int4   d4 = *reinterpret_cast<const int4*>  (in_dst + e);
        float4 w4 = *reinterpret_cast<const float4*>(w_in   + e);
        #pragma unroll
        for (int k = 0; k < 4; k++) {
            int d = (&d4.x)[k] - ASS0;
            int slot = atomicAdd(&g_cnt1[d * CPAD1], 1);
            if (slot < ELL1_S) {
                g_e1src[d * ELL1_S + slot] = (&s4.x)[k];
                g_e1w  [d * ELL1_S + slot] = (&w4.x)[k];
            }
        }
    } else if (e < E_in) {
        for (int k = e; k < E_in; k++) {
            int d = in_dst[k] - ASS0;
            int slot = atomicAdd(&g_cnt1[d * CPAD1], 1);
            if (slot < ELL1_S) {
                g_e1src[d * ELL1_S + slot] = in_src[k];
                g_e1w  [d * ELL1_S + slot] = w_in[k];
            }
        }
    }

    // --- hop2 bucketing: stream src/dst/w wide, keep only dst >= OUT0 ---
    if (e + 4 <= E_ass) {
        int4   s4 = *reinterpret_cast<const int4*>  (ass_src + e);
        int4   d4 = *reinterpret_cast<const int4*>  (ass_dst + e);
        float4 w4 = *reinterpret_cast<const float4*>(w_ass   + e);
        #pragma unroll
        for (int k = 0; k < 4; k++) {
            int d = (&d4.x)[k];
            if (d >= OUT0) {
                int o = d - OUT0;
                int slot = atomicAdd(&g_cnt2[o * CPAD2], 1);
                if (slot < ELL2_S) {
                    g_e2src[o * ELL2_S + slot] = (&s4.x)[k] - ASS0;
                    g_e2w  [o * ELL2_S + slot] = (&w4.x)[k];
                }
            }
        }
    } else if (e < E_ass) {
        for (int k = e; k < E_ass; k++) {
            int d = ass_dst[k];
            if (d >= OUT0) {
                int o = d - OUT0;
                int slot = atomicAdd(&g_cnt2[o * CPAD2], 1);
                if (slot < ELL2_S) {
                    g_e2src[o * ELL2_S + slot] = ass_src[k] - ASS0;
                    g_e2w  [o * ELL2_S + slot] = w_ass[k];
                }
            }
        }
    }
}

// ---------------------------------------------------------------------------
// Kernel B (hop 1): one warp per associative neuron.
// Edges consumed in aligned groups of 4 -> 4 independent 512B row gathers in
// flight (MLP=4). Resets its counter for the next graph replay.
// ---------------------------------------------------------------------------
__global__ void __launch_bounds__(256)
hop1_kernel() {
    const int warp = (blockIdx.x * blockDim.x + threadIdx.x) >> 5;  // 0..4095
    const int lane = threadIdx.x & 31;
    int deg = g_cnt1[warp * CPAD1];
    __syncwarp();
    if (lane == 0) g_cnt1[warp * CPAD1] = 0;  // consume-and-reset
    deg = min(deg, ELL1_S);
    const int base = warp * ELL1_S;           // multiple of 4 -> aligned groups

    float4 acc = make_float4(0.f, 0.f, 0.f, 0.f);
    int j = 0;
    for (; j + 4 <= deg; j += 4) {
        int4   s4 = *reinterpret_cast<const int4*>  (&g_e1src[base + j]);
        float4 w4 = *reinterpret_cast<const float4*>(&g_e1w  [base + j]);
        float4 r0 = *reinterpret_cast<const float4*>(&g_xT[s4.x * BATCH + lane * 4]);
        float4 r1 = *reinterpret_cast<const float4*>(&g_xT[s4.y * BATCH + lane * 4]);
        float4 r2 = *reinterpret_cast<const float4*>(&g_xT[s4.z * BATCH + lane * 4]);
        float4 r3 = *reinterpret_cast<const float4*>(&g_xT[s4.w * BATCH + lane * 4]);
        acc.x += w4.x * r0.x + w4.y * r1.x + w4.z * r2.x + w4.w * r3.x;
        acc.y += w4.x * r0.y + w4.y * r1.y + w4.z * r2.y + w4.w * r3.y;
        acc.z += w4.x * r0.z + w4.y * r1.z + w4.z * r2.z + w4.w * r3.z;
        acc.w += w4.x * r0.w + w4.y * r1.w + w4.z * r2.w + w4.w * r3.w;
    }
    for (; j < deg; j++) {
        int   s = g_e1src[base + j];
        float w = g_e1w  [base + j];
        float4 r = *reinterpret_cast<const float4*>(&g_xT[s * BATCH + lane * 4]);
        acc.x += w * r.x; acc.y += w * r.y; acc.z += w * r.z; acc.w += w * r.w;
    }
    *reinterpret_cast<float4*>(&g_HT[warp * BATCH + lane * 4]) = acc;
}

// ---------------------------------------------------------------------------
// Kernel C (hop 2): one CTA of 16 warps per output neuron.
// Warp g consumes aligned 4-edge groups: int4/float4 edge loads + 4
// independent HT row gathers. Smem tree-reduce, write out[b][o].
// Every out element written -> no zero pass. Resets its counter.
// ---------------------------------------------------------------------------
__global__ void __launch_bounds__(512)
hop2_kernel(float* __restrict__ out) {
    __shared__ float red[16][BATCH];
    const int o    = blockIdx.x;
    const int warp = threadIdx.x >> 5;
    const int lane = threadIdx.x & 31;
    int deg = min(g_cnt2[o * CPAD2], ELL2_S);
    __syncthreads();                               // all reads of counter done
    if (threadIdx.x == 0) g_cnt2[o * CPAD2] = 0;   // consume-and-reset
    const int base = o * ELL2_S;                   // multiple of 4

    float4 acc = make_float4(0.f, 0.f, 0.f, 0.f);
    for (int g = warp; ; g += 16) {
        int j = g * 4;
        if (j >= deg) break;
        int rem = deg - j;
        int4   s4 = *reinterpret_cast<const int4*>  (&g_e2src[base + j]);
        float4 w4 = *reinterpret_cast<const float4*>(&g_e2w  [base + j]);
        {
            float4 r = *reinterpret_cast<const float4*>(&g_HT[s4.x * BATCH + lane * 4]);
            acc.x += w4.x * r.x; acc.y += w4.x * r.y; acc.z += w4.x * r.z; acc.w += w4.x * r.w;
        }
        if (rem > 1) {
            float4 r = *reinterpret_cast<const float4*>(&g_HT[s4.y * BATCH + lane * 4]);
            acc.x += w4.y * r.x; acc.y += w4.y * r.y; acc.z += w4.y * r.z; acc.w += w4.y * r.w;
        }
        if (rem > 2) {
            float4 r = *reinterpret_cast<const float4*>(&g_HT[s4.z * BATCH + lane * 4]);
            acc.x += w4.z * r.x; acc.y += w4.z * r.y; acc.z += w4.z * r.z; acc.w += w4.z * r.w;
        }
        if (rem > 3) {
            float4 r = *reinterpret_cast<const float4*>(&g_HT[s4.w * BATCH + lane * 4]);
            acc.x += w4.w * r.x; acc.y += w4.w * r.y; acc.z += w4.w * r.z; acc.w += w4.w * r.w;
        }
    }
    *reinterpret_cast<float4*>(&red[warp][lane * 4]) = acc;
    __syncthreads();

    if (threadIdx.x < BATCH) {
        float v = 0.f;
        #pragma unroll
        for (int wq = 0; wq < 16; wq++) v += red[wq][threadIdx.x];
        out[threadIdx.x * OUT_F + o] = v;   // out[b][o]
    }
}

// ---------------------------------------------------------------------------
// Launch: 3 kernels
// ---------------------------------------------------------------------------
extern "C" void kernel_launch(void* const* d_in, const int* in_sizes, int n_in,
                              void* d_out, int out_size) {
    const float* x       = (const float*)d_in[0];  // [128, 256]
    const float* w_in    = (const float*)d_in[1];  // [E_in]
    const float* w_ass   = (const float*)d_in[2];  // [E_ass]
    const int*   in_src  = (const int*)  d_in[3];
    const int*   in_dst  = (const int*)  d_in[4];
    const int*   ass_src = (const int*)  d_in[5];
    const int*   ass_dst = (const int*)  d_in[6];

    const int E_in  = in_sizes[1];
    const int E_ass = in_sizes[2];
    float* out = (float*)d_out;

    // Grid covers: transpose (32768 threads), E_in/4 and E_ass/4 edge groups.
    int threads_needed = BATCH * IN_F;              // 32768
    int t1 = (E_in  + 3) / 4;
    int t2 = (E_ass + 3) / 4;
    if (t1 > threads_needed) threads_needed = t1;
    if (t2 > threads_needed) threads_needed = t2;
    int blocks = (threads_needed + 255) / 256;

    build_kernel<<<blocks, 256>>>(x, in_src, in_dst, w_in, E_in,
                                  ass_src, ass_dst, w_ass, E_ass);
    hop1_kernel <<<(N_ASS * 32) / 256, 256>>>();   // 512 CTAs, 1 warp/assoc
    hop2_kernel <<<OUT_F, 512>>>(out);             // 256 CTAs, 16 warps/output
}

// round 17
// speedup vs baseline: 1.0503x; 1.0503x over previous
#include <cuda_runtime.h>
#include <cuda_fp16.h>

// Problem constants (fixed by reference_code)
#define IN_F   256
#define N_ASS  4096
#define OUT_F  256
#define BATCH  128
#define ASS0   IN_F            // 256  : first associative neuron index
#define OUT0   (IN_F + N_ASS)  // 4352 : first output neuron index

// hop1 ELL: in-degree ~ Bin(256,0.05) mean 12.8 sd 3.5 -> 64 slots (14 sigma)
#define ELL1_S 64

// hop2 ELL is SHARDED: R15 showed build stuck at issue=9.8% from ~205
// serialized RMW ops per cnt2 address (~30cyc each -> ~3k cyc avg queue).
// 16 sub-counters per output (shard = thread & 15, deterministic) cut
// per-address contention to ~13. Bin(205,1/16): mean 12.8 sd 3.47 -> 40
// slots is ~7.8 sigma against overflow.
#define NSHARD      16
#define SHARD_SLOTS 40
#define ELL2_S      (NSHARD * SHARD_SLOTS)   // 640

// Counter padding: 256B stride keeps counters on distinct L2 slice-groups
// (hash bits {8,10-27}; R6->R7 showed 4B-contiguous collapses onto ~4).
#define CPAD1 64
#define CPAD2 64

// Device scratch (no runtime allocation). Zero-initialized at load; hop
// kernels re-zero counters after consuming them -> every graph replay sees
// zeros on entry to build.
__device__ __align__(16) float  g_xT  [IN_F  * BATCH];   // x transposed
__device__ __align__(16) __half g_HTh [N_ASS * BATCH];   // hidden acts, fp16
__device__ int   g_cnt1[N_ASS * CPAD1];
__device__ int   g_cnt2[OUT_F * NSHARD * CPAD2];
__device__ __align__(16) int   g_e1src[N_ASS * ELL1_S];
__device__ __align__(16) float g_e1w  [N_ASS * ELL1_S];
__device__ __align__(16) int   g_e2src[OUT_F * ELL2_S];
__device__ __align__(16) float g_e2w  [OUT_F * ELL2_S];

// ---------------------------------------------------------------------------
// Kernel A (fused): transpose x -> xT, bucket hop1 edges, bucket hop2 edges
// (keep only dst >= OUT0; assoc->assoc edges never reach the output).
// Edge arrays streamed as front-batched int4/float4 (MLP=3).
// ---------------------------------------------------------------------------
__global__ void __launch_bounds__(256)
build_kernel(const float* __restrict__ x,
             const int* __restrict__ in_src, const int* __restrict__ in_dst,
             const float* __restrict__ w_in, int E_in,
             const int* __restrict__ ass_src, const int* __restrict__ ass_dst,
             const float* __restrict__ w_ass, int E_ass) {
    const int t = blockIdx.x * blockDim.x + threadIdx.x;

    // --- transpose x (32768 elems) ---
    if (t < BATCH * IN_F) {
        int b = t >> 8;          // / IN_F
        int i = t & (IN_F - 1);  // % IN_F
        g_xT[i * BATCH + b] = x[t];
    }

    const int e     = t * 4;
    const int shard = t & (NSHARD - 1);   // deterministic per-edge shard

    // --- hop1 bucketing: 4 edges/thread, contention ~13 per counter ---
    if (e + 4 <= E_in) {
        int4   s4 = *reinterpret_cast<const int4*>  (in_src + e);
        int4   d4 = *reinterpret_cast<const int4*>  (in_dst + e);
        float4 w4 = *reinterpret_cast<const float4*>(w_in   + e);
        #pragma unroll
        for (int k = 0; k < 4; k++) {
            int d = (&d4.x)[k] - ASS0;
            int slot = atomicAdd(&g_cnt1[d * CPAD1], 1);
            if (slot < ELL1_S) {
                g_e1src[d * ELL1_S + slot] = (&s4.x)[k];
                g_e1w  [d * ELL1_S + slot] = (&w4.x)[k];
            }
        }
    } else if (e < E_in) {
        for (int k = e; k < E_in; k++) {
            int d = in_dst[k] - ASS0;
            int slot = atomicAdd(&g_cnt1[d * CPAD1], 1);
            if (slot < ELL1_S) {
                g_e1src[d * ELL1_S + slot] = in_src[k];
                g_e1w  [d * ELL1_S + slot] = w_in[k];
            }
        }
    }

    // --- hop2 bucketing: sharded sub-counters (contention 205 -> ~13) ---
    if (e + 4 <= E_ass) {
        int4   s4 = *reinterpret_cast<const int4*>  (ass_src + e);
        int4   d4 = *reinterpret_cast<const int4*>  (ass_dst + e);
        float4 w4 = *reinterpret_cast<const float4*>(w_ass   + e);
        #pragma unroll
        for (int k = 0; k < 4; k++) {
            int d = (&d4.x)[k];
            if (d >= OUT0) {
                int o = d - OUT0;
                int slot = atomicAdd(&g_cnt2[(o * NSHARD + shard) * CPAD2], 1);
                if (slot < SHARD_SLOTS) {
                    int idx = o * ELL2_S + shard * SHARD_SLOTS + slot;
                    g_e2src[idx] = (&s4.x)[k] - ASS0;
                    g_e2w  [idx] = (&w4.x)[k];
                }
            }
        }
    } else if (e < E_ass) {
        for (int k = e; k < E_ass; k++) {
            int d = ass_dst[k];
            if (d >= OUT0) {
                int o = d - OUT0;
                int slot = atomicAdd(&g_cnt2[(o * NSHARD + shard) * CPAD2], 1);
                if (slot < SHARD_SLOTS) {
                    int idx = o * ELL2_S + shard * SHARD_SLOTS + slot;
                    g_e2src[idx] = ass_src[k] - ASS0;
                    g_e2w  [idx] = w_ass[k];
                }
            }
        }
    }
}

// ---------------------------------------------------------------------------
// Kernel B (hop 1): one warp per associative neuron.
// Aligned 4-edge groups -> 4 independent 512B xT row gathers (MLP=4).
// Accumulate fp32, store HT row as fp16 (halves hop2's gather traffic;
// round-to-nearest rel rms ~1.4e-4 << 1e-3 gate). Resets its counter.
// ---------------------------------------------------------------------------
__global__ void __launch_bounds__(256)
hop1_kernel() {
    const int warp = (blockIdx.x * blockDim.x + threadIdx.x) >> 5;  // 0..4095
    const int lane = threadIdx.x & 31;
    int deg = g_cnt1[warp * CPAD1];
    __syncwarp();
    if (lane == 0) g_cnt1[warp * CPAD1] = 0;  // consume-and-reset
    deg = min(deg, ELL1_S);
    const int base = warp * ELL1_S;           // multiple of 4 -> aligned groups

    float4 acc = make_float4(0.f, 0.f, 0.f, 0.f);
    int j = 0;
    for (; j + 4 <= deg; j += 4) {
        int4   s4 = *reinterpret_cast<const int4*>  (&g_e1src[base + j]);
        float4 w4 = *reinterpret_cast<const float4*>(&g_e1w  [base + j]);
        float4 r0 = *reinterpret_cast<const float4*>(&g_xT[s4.x * BATCH + lane * 4]);
        float4 r1 = *reinterpret_cast<const float4*>(&g_xT[s4.y * BATCH + lane * 4]);
        float4 r2 = *reinterpret_cast<const float4*>(&g_xT[s4.z * BATCH + lane * 4]);
        float4 r3 = *reinterpret_cast<const float4*>(&g_xT[s4.w * BATCH + lane * 4]);
        acc.x += w4.x * r0.x + w4.y * r1.x + w4.z * r2.x + w4.w * r3.x;
        acc.y += w4.x * r0.y + w4.y * r1.y + w4.z * r2.y + w4.w * r3.y;
        acc.z += w4.x * r0.z + w4.y * r1.z + w4.z * r2.z + w4.w * r3.z;
        acc.w += w4.x * r0.w + w4.y * r1.w + w4.z * r2.w + w4.w * r3.w;
    }
    for (; j < deg; j++) {
        int   s = g_e1src[base + j];
        float w = g_e1w  [base + j];
        float4 r = *reinterpret_cast<const float4*>(&g_xT[s * BATCH + lane * 4]);
        acc.x += w * r.x; acc.y += w * r.y; acc.z += w * r.z; acc.w += w * r.w;
    }
    // pack 4 fp32 -> 4 fp16 (batch order preserved: low half first)
    __half2 pk[2];
    pk[0] = __floats2half2_rn(acc.x, acc.y);
    pk[1] = __floats2half2_rn(acc.z, acc.w);
    *reinterpret_cast<uint2*>(&g_HTh[warp * BATCH + lane * 4]) =
        *reinterpret_cast<uint2*>(pk);
}

// ---------------------------------------------------------------------------
// Kernel C (hop 2): one CTA of 16 warps per output neuron; warp w consumes
// shard w (~13 edges) in aligned 4-groups: int4/float4 edge loads + 4
// independent 256B fp16 HT row gathers. fp32 accumulate, smem tree-reduce,
// write out[b][o]. Every out element written -> no zero pass. Resets its
// sub-counter.
// ---------------------------------------------------------------------------
__global__ void __launch_bounds__(512)
hop2_kernel(float* __restrict__ out) {
    __shared__ float red[16][BATCH];
    const int o    = blockIdx.x;
    const int warp = threadIdx.x >> 5;
    const int lane = threadIdx.x & 31;
    int deg = g_cnt2[(o * NSHARD + warp) * CPAD2];
    __syncwarp();
    if (lane == 0) g_cnt2[(o * NSHARD + warp) * CPAD2] = 0;  // consume-and-reset
    deg = min(deg, SHARD_SLOTS);
    const int sbase = o * ELL2_S + warp * SHARD_SLOTS;       // multiple of 4

    float4 acc = make_float4(0.f, 0.f, 0.f, 0.f);
    int j = 0;
    for (; j + 4 <= deg; j += 4) {
        int4   s4 = *reinterpret_cast<const int4*>  (&g_e2src[sbase + j]);
        float4 w4 = *reinterpret_cast<const float4*>(&g_e2w  [sbase + j]);
        uint2 u0 = *reinterpret_cast<const uint2*>(&g_HTh[s4.x * BATCH + lane * 4]);
        uint2 u1 = *reinterpret_cast<const uint2*>(&g_HTh[s4.y * BATCH + lane * 4]);
        uint2 u2 = *reinterpret_cast<const uint2*>(&g_HTh[s4.z * BATCH + lane * 4]);
        uint2 u3 = *reinterpret_cast<const uint2*>(&g_HTh[s4.w * BATCH + lane * 4]);
        {
            float2 a = __half22float2(*reinterpret_cast<__half2*>(&u0.x));
            float2 b = __half22float2(*reinterpret_cast<__half2*>(&u0.y));
            acc.x += w4.x * a.x; acc.y += w4.x * a.y;
            acc.z += w4.x * b.x; acc.w += w4.x * b.y;
        }
        {
            float2 a = __half22float2(*reinterpret_cast<__half2*>(&u1.x));
            float2 b = __half22float2(*reinterpret_cast<__half2*>(&u1.y));
            acc.x += w4.y * a.x; acc.y += w4.y * a.y;
            acc.z += w4.y * b.x; acc.w += w4.y * b.y;
        }
        {
            float2 a = __half22float2(*reinterpret_cast<__half2*>(&u2.x));
            float2 b = __half22float2(*reinterpret_cast<__half2*>(&u2.y));
            acc.x += w4.z * a.x; acc.y += w4.z * a.y;
            acc.z += w4.z * b.x; acc.w += w4.z * b.y;
        }
        {
            float2 a = __half22float2(*reinterpret_cast<__half2*>(&u3.x));
            float2 b = __half22float2(*reinterpret_cast<__half2*>(&u3.y));
            acc.x += w4.w * a.x; acc.y += w4.w * a.y;
            acc.z += w4.w * b.x; acc.w += w4.w * b.y;
        }
    }
    for (; j < deg; j++) {
        int   s = g_e2src[sbase + j];
        float w = g_e2w  [sbase + j];
        uint2 u = *reinterpret_cast<const uint2*>(&g_HTh[s * BATCH + lane * 4]);
        float2 a = __half22float2(*reinterpret_cast<__half2*>(&u.x));
        float2 b = __half22float2(*reinterpret_cast<__half2*>(&u.y));
        acc.x += w * a.x; acc.y += w * a.y;
        acc.z += w * b.x; acc.w += w * b.y;
    }
    *reinterpret_cast<float4*>(&red[warp][lane * 4]) = acc;
    __syncthreads();

    if (threadIdx.x < BATCH) {
        float v = 0.f;
        #pragma unroll
        for (int wq = 0; wq < 16; wq++) v += red[wq][threadIdx.x];
        out[threadIdx.x * OUT_F + o] = v;   // out[b][o]
    }
}

// ---------------------------------------------------------------------------
// Launch: 3 kernels
// ---------------------------------------------------------------------------
extern "C" void kernel_launch(void* const* d_in, const int* in_sizes, int n_in,
                              void* d_out, int out_size) {
    const float* x       = (const float*)d_in[0];  // [128, 256]
    const float* w_in    = (const float*)d_in[1];  // [E_in]
    const float* w_ass   = (const float*)d_in[2];  // [E_ass]
    const int*   in_src  = (const int*)  d_in[3];
    const int*   in_dst  = (const int*)  d_in[4];
    const int*   ass_src = (const int*)  d_in[5];
    const int*   ass_dst = (const int*)  d_in[6];

    const int E_in  = in_sizes[1];
    const int E_ass = in_sizes[2];
    float* out = (float*)d_out;

    // Grid covers: transpose (32768 threads), E_in/4 and E_ass/4 edge groups.
    int threads_needed = BATCH * IN_F;              // 32768
    int t1 = (E_in  + 3) / 4;
    int t2 = (E_ass + 3) / 4;
    if (t1 > threads_needed) threads_needed = t1;
    if (t2 > threads_needed) threads_needed = t2;
    int blocks = (threads_needed + 255) / 256;

    build_kernel<<<blocks, 256>>>(x, in_src, in_dst, w_in, E_in,
                                  ass_src, ass_dst, w_ass, E_ass);
    hop1_kernel <<<(N_ASS * 32) / 256, 256>>>();   // 512 CTAs, 1 warp/assoc
    hop2_kernel <<<OUT_F, 512>>>(out);             // 256 CTAs, 16 warps/output
}